// round 10
// baseline (speedup 1.0000x reference)
#include <cuda_runtime.h>
#include <cstdint>

#define B    64
#define IN   64
#define H    512
#define L    128
#define NCTA 128
#define NT   256
#define JT   4      // hidden units per CTA (128*4 = 512)

// ---------------- persistent scratch (no allocations allowed) ----------------
__device__ float g_h[2][H * B];      // hidden state, transposed [j][b], double buffered
__device__ float g_z[L * B];         // latent z, transposed [l][b]
__device__ float g_cw[3 * H * H];    // folded decoder weights: [comb_r | comb_z | M_n] rows
__device__ volatile unsigned int g_arr[NCTA * 8];   // per-CTA arrival flags (padded 32B)
__device__ volatile unsigned int g_gen;             // release generation

// ---------------- packed fp32x2 helpers (sm_100+ PTX) ------------------------
__device__ __forceinline__ unsigned long long packf2(float lo, float hi) {
    unsigned long long r;
    asm("mov.b64 %0, {%1, %2};" : "=l"(r) : "f"(lo), "f"(hi));
    return r;
}
__device__ __forceinline__ float sumf2(unsigned long long v) {
    float lo, hi;
    asm("mov.b64 {%0, %1}, %2;" : "=f"(lo), "=f"(hi) : "l"(v));
    return lo + hi;
}
__device__ __forceinline__ void ffma2(unsigned long long& d,
                                      unsigned long long a, unsigned long long b) {
    asm("fma.rn.f32x2 %0, %1, %2, %0;" : "+l"(d) : "l"(a), "l"(b));
}

// ------- software grid barrier: flag fan-in + leader-CTA release -------------
// No same-address atomic serialization: each CTA stores to its own flag; CTA 0's
// first NCTA threads poll the flags in parallel, then thread 0 releases g_gen.
__device__ __forceinline__ void grid_barrier(unsigned int target, int c) {
    __threadfence();           // publish this CTA's global writes
    __syncthreads();
    const int tid = threadIdx.x;
    if (c == 0) {
        if (tid == 0) g_arr[0] = target;
        if (tid < NCTA) {
            while (g_arr[tid * 8] < target) { }
        }
        __syncthreads();       // all flags observed by the CTA
        if (tid == 0) { __threadfence(); g_gen = target; }
        __threadfence();
    } else {
        if (tid == 0) {
            g_arr[c * 8] = target;
            while (g_gen < target) { }
            __threadfence();
        }
        __syncthreads();
    }
}

__device__ __forceinline__ float sigmoidf_(float v) {
    return 1.0f / (1.0f + expf(-v));
}

__global__ void init_kernel() {
    int idx = blockIdx.x * blockDim.x + threadIdx.x;
    // MUST reset ALL barrier state every launch: the harness replays the
    // captured graph many times and bt restarts from 1 each replay.
    if (idx < NCTA * 8) g_arr[idx] = 0u;
    if (idx == 0) g_gen = 0u;
    if (idx < H * B) g_h[0][idx] = 0.0f;
}

// Fold decoder feedback into recurrence weights:
//   gblk 0 (r): comb = dec_W_hh_r + dec_W_ih_r @ out_W
//   gblk 1 (z): comb = dec_W_hh_z + dec_W_ih_z @ out_W
//   gblk 2 (n): M_n  =              dec_W_ih_n @ out_W
__global__ void fold_kernel(const float* __restrict__ dWih,
                            const float* __restrict__ dWhh,
                            const float* __restrict__ oW) {
    __shared__ float row[IN];
    const int blk = blockIdx.x;          // 0 .. 3*H*2-1
    const int r   = blk >> 1;            // gate-row 0..3H-1
    const int kb  = (blk & 1) * 256;
    if (threadIdx.x < IN) row[threadIdx.x] = dWih[(size_t)r * IN + threadIdx.x];
    __syncthreads();
    const int k = kb + threadIdx.x;
    float acc = 0.f;
#pragma unroll 8
    for (int i = 0; i < IN; ++i)
        acc = fmaf(row[i], oW[(size_t)i * H + k], acc);
    if (r < 2 * H) acc += dWhh[(size_t)r * H + k];
    g_cw[(size_t)r * H + k] = acc;
}

__global__ void __launch_bounds__(NT, 1)
gruvae_kernel(const float* __restrict__ x,    const float* __restrict__ eps,
              const float* __restrict__ eWih, const float* __restrict__ eWhh,
              const float* __restrict__ ebih, const float* __restrict__ ebhh,
              const float* __restrict__ muW,  const float* __restrict__ mub,
              const float* __restrict__ lvW,  const float* __restrict__ lvb,
              const float* __restrict__ l2hW, const float* __restrict__ l2hb,
              const float* __restrict__ dWih, const float* __restrict__ dWhh,
              const float* __restrict__ dbih, const float* __restrict__ dbhh,
              const float* __restrict__ oW,   const float* __restrict__ ob,
              float* __restrict__ out, int T)
{
    extern __shared__ float smem[];
    float* ws   = smem;              // [8192]  weight rows (enc: 12 used, dec: 16)
    float* wx   = smem + 8192;       // [768]   W_ih slice (encoder only)
    float* ow   = smem + 8960;       // [512]   out_W row icol (decoder)
    float* pool = smem + 9472;       // [4416]  x staging / partial sums

    const int tid = threadIdx.x, c = blockIdx.x;
    const int b  = tid & 63;          // batch lane
    const int q  = tid >> 6;          // dual role: k-chunk (partials) / local unit j (finalize)
    const int jg = c * JT + q;        // global hidden unit (finalize role)
    unsigned int bt = 0;

    // ---- load encoder weight slices into smem ----
    for (int u = tid; u < 3 * JT * H; u += NT) {
        int gj = u / H, k = u - gj * H;
        int g = gj / JT, jj = gj - g * JT;
        ws[u] = eWhh[(size_t)(g * H + c * JT + jj) * H + k];
    }
    for (int u = tid; u < 3 * JT * IN; u += NT) {
        int gj = u / IN, k = u - gj * IN;
        int g = gj / JT, jj = gj - g * JT;
        wx[u] = eWih[(size_t)(g * H + c * JT + jj) * IN + k];
    }
    float bihr = __ldg(ebih + jg), bihz = __ldg(ebih + H + jg), bihn = __ldg(ebih + 2 * H + jg);
    float bhhr = __ldg(ebhh + jg), bhhz = __ldg(ebhh + H + jg), bhhn = __ldg(ebhh + 2 * H + jg);
    __syncthreads();

    const float* vr = wx + (0 * JT + q) * IN;
    const float* vz = wx + (1 * JT + q) * IN;
    const float* vn = wx + (2 * JT + q) * IN;

    const size_t MU_OFF = (size_t)B * T * IN;
    const size_t LV_OFF = MU_OFF + (size_t)B * L;

    const int kbase = q * 128;        // this thread's k-chunk for the hh GEMM
    const int xb = tid >> 4, xq = tid & 15;   // x prefetch lane mapping
    int cur = 0;

    // h_own: this thread's own h[jg][b] (it is the thread that writes it each step)
    float h_own = 0.0f;               // g_h[0] is zeroed

    // ---- prefetch x tile for t=0 ----
    float4 xv0, xv1, xv2, xv3;
    {
        const float4* xp = reinterpret_cast<const float4*>(x) + xq;
        xv0 = __ldg(xp + ((size_t)(xb +  0) * T + 0) * (IN / 4));
        xv1 = __ldg(xp + ((size_t)(xb + 16) * T + 0) * (IN / 4));
        xv2 = __ldg(xp + ((size_t)(xb + 32) * T + 0) * (IN / 4));
        xv3 = __ldg(xp + ((size_t)(xb + 48) * T + 0) * (IN / 4));
    }

    // ================= encoder scan =================
    for (int t = 0; t < T; ++t) {
        // commit prefetched x[:, t, :] (transposed) into pool
        {
            float4 v; int bb;
#pragma unroll
            for (int r = 0; r < 4; ++r) {
                v  = (r == 0) ? xv0 : (r == 1) ? xv1 : (r == 2) ? xv2 : xv3;
                bb = xb + 16 * r;
                pool[(4 * xq + 0) * 65 + bb] = v.x;
                pool[(4 * xq + 1) * 65 + bb] = v.y;
                pool[(4 * xq + 2) * 65 + bb] = v.z;
                pool[(4 * xq + 3) * 65 + bb] = v.w;
            }
        }
        __syncthreads();

        // ---- k-split hh partials, packed f32x2 (role (b, kc=q)) ----
        const float* hb = g_h[cur] + b;
        unsigned long long pacc[12];
#pragma unroll
        for (int m = 0; m < 12; ++m) pacc[m] = 0ULL;
#pragma unroll 4
        for (int k = kbase; k < kbase + 128; k += 4) {
            float h0 = __ldcg(hb + (k + 0) * B);
            float h1 = __ldcg(hb + (k + 1) * B);
            float h2 = __ldcg(hb + (k + 2) * B);
            float h3 = __ldcg(hb + (k + 3) * B);
            unsigned long long h01 = packf2(h0, h1);
            unsigned long long h23 = packf2(h2, h3);
#pragma unroll
            for (int m = 0; m < 12; ++m) {
                ulonglong2 w = *reinterpret_cast<const ulonglong2*>(ws + m * H + k);
                ffma2(pacc[m], h01, w.x);
                ffma2(pacc[m], h23, w.y);
            }
        }

        // ---- input-gate dot for role (b, j=q), while pool still holds x_t ----
        float xr = 0.f, xz = 0.f, xn = 0.f;
#pragma unroll 4
        for (int k = 0; k < IN; k += 4) {
            float x0 = pool[(k + 0) * 65 + b];
            float x1 = pool[(k + 1) * 65 + b];
            float x2 = pool[(k + 2) * 65 + b];
            float x3 = pool[(k + 3) * 65 + b];
            float4 wa = *reinterpret_cast<const float4*>(vr + k);
            float4 wb = *reinterpret_cast<const float4*>(vz + k);
            float4 wc = *reinterpret_cast<const float4*>(vn + k);
            xr = fmaf(x0, wa.x, fmaf(x1, wa.y, fmaf(x2, wa.z, fmaf(x3, wa.w, xr))));
            xz = fmaf(x0, wb.x, fmaf(x1, wb.y, fmaf(x2, wb.z, fmaf(x3, wb.w, xz))));
            xn = fmaf(x0, wc.x, fmaf(x1, wc.y, fmaf(x2, wc.z, fmaf(x3, wc.w, xn))));
        }
        __syncthreads();                       // all pool (x) reads done

        // ---- prefetch x for t+1 (hidden under reduction + barrier) ----
        if (t + 1 < T) {
            const float4* xp = reinterpret_cast<const float4*>(x) + xq;
            xv0 = __ldg(xp + ((size_t)(xb +  0) * T + (t + 1)) * (IN / 4));
            xv1 = __ldg(xp + ((size_t)(xb + 16) * T + (t + 1)) * (IN / 4));
            xv2 = __ldg(xp + ((size_t)(xb + 32) * T + (t + 1)) * (IN / 4));
            xv3 = __ldg(xp + ((size_t)(xb + 48) * T + (t + 1)) * (IN / 4));
        }

        // ---- publish partials into pool ----
#pragma unroll
        for (int m = 0; m < 12; ++m)
            pool[(q * 12 + m) * 64 + b] = sumf2(pacc[m]);
        __syncthreads();

        // ---- finalize gates (role (b, j=q)) ----
        float ar = 0.f, az = 0.f, an = 0.f;
#pragma unroll
        for (int kc = 0; kc < 4; ++kc) {
            ar += pool[(kc * 12 + 0 + q) * 64 + b];
            az += pool[(kc * 12 + 4 + q) * 64 + b];
            an += pool[(kc * 12 + 8 + q) * 64 + b];
        }
        float r_ = sigmoidf_(xr + bihr + ar + bhhr);
        float z_ = sigmoidf_(xz + bihz + az + bhhz);
        float n_ = tanhf(xn + bihn + r_ * (an + bhhn));
        h_own = (1.f - z_) * n_ + z_ * h_own;
        g_h[cur ^ 1][jg * B + b] = h_own;

        grid_barrier(++bt, c);
        cur ^= 1;
    }

    // ================= latent block =================
    {
        const float* hn = g_h[cur];
        if (tid < B) {
            const int l = c, bb = tid;
            const float* hb2 = hn + bb;
            float am = 0.f, av = 0.f;
#pragma unroll 8
            for (int k = 0; k < H; ++k) {
                float hv = __ldcg(hb2 + k * B);
                am = fmaf(hv, __ldg(muW + (size_t)l * H + k), am);
                av = fmaf(hv, __ldg(lvW + (size_t)l * H + k), av);
            }
            float mu = am + __ldg(mub + l);
            float lv = av + __ldg(lvb + l);
            out[MU_OFF + (size_t)bb * L + l] = mu;
            out[LV_OFF + (size_t)bb * L + l] = lv;
            g_z[l * B + bb] = mu + __ldg(eps + bb * L + l) * expf(0.5f * lv);
        }
    }
    grid_barrier(++bt, c);   // latent reads of h_n done; z published

    // h_dec = z @ l2h_W^T + l2h_b   (role (b, j=q)) — overwrites g_h[cur]
    {
        float acc = 0.f;
        const float* zb = g_z + b;
#pragma unroll 8
        for (int l = 0; l < L; ++l)
            acc = fmaf(__ldcg(zb + l * B), __ldg(l2hW + (size_t)jg * L + l), acc);
        h_own = acc + __ldg(l2hb + jg);
        g_h[cur][jg * B + b] = h_own;
    }

    // ---- load plain dWhh rows for decoder step 0 (inp = 0 -> gx = b_ih) ----
    for (int u = tid; u < 3 * JT * H; u += NT) {
        int gj = u / H, k = u - gj * H;
        int g = gj / JT, jj = gj - g * JT;
        ws[u] = dWhh[(size_t)(g * H + c * JT + jj) * H + k];
    }
    float bihr2 = __ldg(dbih + jg), bihz2 = __ldg(dbih + H + jg), bihn2 = __ldg(dbih + 2 * H + jg);
    bhhr = __ldg(dbhh + jg); bhhz = __ldg(dbhh + H + jg); bhhn = __ldg(dbhh + 2 * H + jg);
    __syncthreads();
    grid_barrier(++bt, c);   // h_dec visible everywhere

    // ================= decoder step 0: h_0 from h_dec =================
    {
        const float* hb = g_h[cur] + b;
        unsigned long long pacc[12];
#pragma unroll
        for (int m = 0; m < 12; ++m) pacc[m] = 0ULL;
#pragma unroll 4
        for (int k = kbase; k < kbase + 128; k += 4) {
            float h0 = __ldcg(hb + (k + 0) * B);
            float h1 = __ldcg(hb + (k + 1) * B);
            float h2 = __ldcg(hb + (k + 2) * B);
            float h3 = __ldcg(hb + (k + 3) * B);
            unsigned long long h01 = packf2(h0, h1);
            unsigned long long h23 = packf2(h2, h3);
#pragma unroll
            for (int m = 0; m < 12; ++m) {
                ulonglong2 w = *reinterpret_cast<const ulonglong2*>(ws + m * H + k);
                ffma2(pacc[m], h01, w.x);
                ffma2(pacc[m], h23, w.y);
            }
        }
#pragma unroll
        for (int m = 0; m < 12; ++m)
            pool[(q * 12 + m) * 64 + b] = sumf2(pacc[m]);
        __syncthreads();
        float ar = 0.f, az = 0.f, an = 0.f;
#pragma unroll
        for (int kc = 0; kc < 4; ++kc) {
            ar += pool[(kc * 12 + 0 + q) * 64 + b];
            az += pool[(kc * 12 + 4 + q) * 64 + b];
            an += pool[(kc * 12 + 8 + q) * 64 + b];
        }
        float r_ = sigmoidf_(bihr2 + ar + bhhr);
        float z_ = sigmoidf_(bihz2 + az + bhhz);
        float n_ = tanhf(bihn2 + r_ * (an + bhhn));
        h_own = (1.f - z_) * n_ + z_ * h_own;
        g_h[cur ^ 1][jg * B + b] = h_own;
        grid_barrier(++bt, c);   // h_0 ready
        cur ^= 1;
    }

    // ---- load folded decoder weights: 16 rows [comb_r | comb_z | M_n | Whh_n] ----
    for (int u = tid; u < 4 * JT * H; u += NT) {
        int gj = u / H, k = u - gj * H;
        int g = gj / JT, jj = gj - g * JT;     // g = 0..3
        ws[u] = (g < 3) ? g_cw[(size_t)(g * H + c * JT + jj) * H + k]
                        : dWhh[(size_t)(2 * H + c * JT + jj) * H + k];
    }
    const int  icol   = c >> 1;             // out column this CTA folds (pairs duplicate)
    const bool writer = ((c & 1) == 0);     // even CTA of the pair publishes
    for (int u = tid; u < H; u += NT) ow[u] = __ldg(oW + (size_t)icol * H + u);
    // cb = W_ih @ ob + b_ih  (per gate, this thread's unit)
    float cbr, cbz, cbn;
    {
        float s0 = 0.f, s1 = 0.f, s2 = 0.f;
#pragma unroll 8
        for (int i = 0; i < IN; ++i) {
            float o = __ldg(ob + i);
            s0 = fmaf(__ldg(dWih + (size_t)(0 * H + jg) * IN + i), o, s0);
            s1 = fmaf(__ldg(dWih + (size_t)(1 * H + jg) * IN + i), o, s1);
            s2 = fmaf(__ldg(dWih + (size_t)(2 * H + jg) * IN + i), o, s2);
        }
        cbr = s0 + bihr2; cbz = s1 + bihz2; cbn = s2 + bihn2;
    }
    const float outb = __ldg(ob + icol);
    __syncthreads();

    // ================= decoder scan (folded feedback): t = 1 .. T-1 =================
    for (int t = 1; t < T; ++t) {
        const float* hb = g_h[cur] + b;     // h_{t-1}

        // 16 folded rows + out_W row, packed f32x2
        unsigned long long pacc[16];
#pragma unroll
        for (int m = 0; m < 16; ++m) pacc[m] = 0ULL;
        unsigned long long poacc = 0ULL;
#pragma unroll 4
        for (int k = kbase; k < kbase + 128; k += 4) {
            float h0 = __ldcg(hb + (k + 0) * B);
            float h1 = __ldcg(hb + (k + 1) * B);
            float h2 = __ldcg(hb + (k + 2) * B);
            float h3 = __ldcg(hb + (k + 3) * B);
            unsigned long long h01 = packf2(h0, h1);
            unsigned long long h23 = packf2(h2, h3);
#pragma unroll
            for (int m = 0; m < 16; ++m) {
                ulonglong2 w = *reinterpret_cast<const ulonglong2*>(ws + m * H + k);
                ffma2(pacc[m], h01, w.x);
                ffma2(pacc[m], h23, w.y);
            }
            ulonglong2 wo = *reinterpret_cast<const ulonglong2*>(ow + k);
            ffma2(poacc, h01, wo.x);
            ffma2(poacc, h23, wo.y);
        }

        // publish all partials (17 rows per k-chunk)
#pragma unroll
        for (int m = 0; m < 16; ++m)
            pool[(q * 17 + m) * 64 + b] = sumf2(pacc[m]);
        pool[(q * 17 + 16) * 64 + b] = sumf2(poacc);
        __syncthreads();

        // writer: out_{t-1} = h_{t-1} @ out_W^T + out_b  (off critical path, no grid sync)
        if (writer && tid < B) {
            float s = pool[(0 * 17 + 16) * 64 + tid] + pool[(1 * 17 + 16) * 64 + tid]
                    + pool[(2 * 17 + 16) * 64 + tid] + pool[(3 * 17 + 16) * 64 + tid];
            out[((size_t)tid * T + (t - 1)) * IN + icol] = s + outb;
        }

        // finalize gates: r,z combined; n split
        float ar = 0.f, az = 0.f, gxn = 0.f, ghn = 0.f;
#pragma unroll
        for (int kc = 0; kc < 4; ++kc) {
            ar  += pool[(kc * 17 +  0 + q) * 64 + b];
            az  += pool[(kc * 17 +  4 + q) * 64 + b];
            gxn += pool[(kc * 17 +  8 + q) * 64 + b];
            ghn += pool[(kc * 17 + 12 + q) * 64 + b];
        }
        float r_ = sigmoidf_(ar + cbr + bhhr);
        float z_ = sigmoidf_(az + cbz + bhhz);
        float n_ = tanhf(gxn + cbn + r_ * (ghn + bhhn));
        h_own = (1.f - z_) * n_ + z_ * h_own;
        g_h[cur ^ 1][jg * B + b] = h_own;

        grid_barrier(++bt, c);   // h_t ready
        cur ^= 1;
    }

    // final output row: out_{T-1} = h_{T-1} @ out_W^T + out_b
    {
        const float* hb = g_h[cur] + b;
        unsigned long long poacc = 0ULL;
#pragma unroll 4
        for (int k = kbase; k < kbase + 128; k += 4) {
            float h0 = __ldcg(hb + (k + 0) * B);
            float h1 = __ldcg(hb + (k + 1) * B);
            float h2 = __ldcg(hb + (k + 2) * B);
            float h3 = __ldcg(hb + (k + 3) * B);
            ulonglong2 wo = *reinterpret_cast<const ulonglong2*>(ow + k);
            ffma2(poacc, packf2(h0, h1), wo.x);
            ffma2(poacc, packf2(h2, h3), wo.y);
        }
        pool[(q * 17 + 16) * 64 + b] = sumf2(poacc);
        __syncthreads();
        if (writer && tid < B) {
            float s = pool[(0 * 17 + 16) * 64 + tid] + pool[(1 * 17 + 16) * 64 + tid]
                    + pool[(2 * 17 + 16) * 64 + tid] + pool[(3 * 17 + 16) * 64 + tid];
            out[((size_t)tid * T + (T - 1)) * IN + icol] = s + outb;
        }
    }
}

extern "C" void kernel_launch(void* const* d_in, const int* in_sizes, int n_in,
                              void* d_out, int out_size) {
    const float* x    = (const float*)d_in[0];
    const float* eps  = (const float*)d_in[1];
    const float* eWih = (const float*)d_in[2];
    const float* eWhh = (const float*)d_in[3];
    const float* ebih = (const float*)d_in[4];
    const float* ebhh = (const float*)d_in[5];
    const float* muW  = (const float*)d_in[6];
    const float* mub  = (const float*)d_in[7];
    const float* lvW  = (const float*)d_in[8];
    const float* lvb  = (const float*)d_in[9];
    const float* l2hW = (const float*)d_in[10];
    const float* l2hb = (const float*)d_in[11];
    const float* dWih = (const float*)d_in[12];
    const float* dWhh = (const float*)d_in[13];
    const float* dbih = (const float*)d_in[14];
    const float* dbhh = (const float*)d_in[15];
    const float* oW   = (const float*)d_in[16];
    const float* ob   = (const float*)d_in[17];
    float* out = (float*)d_out;

    const int T = in_sizes[0] / (B * IN);
    const int SMEM_BYTES = (8192 + 768 + 512 + 4416) * 4;   // 55552

    cudaFuncSetAttribute(gruvae_kernel,
                         cudaFuncAttributeMaxDynamicSharedMemorySize, SMEM_BYTES);

    init_kernel<<<(H * B + 255) / 256, 256>>>();
    fold_kernel<<<3 * H * 2, 256>>>(dWih, dWhh, oW);
    gruvae_kernel<<<NCTA, NT, SMEM_BYTES>>>(x, eps, eWih, eWhh, ebih, ebhh,
                                            muW, mub, lvW, lvb, l2hW, l2hb,
                                            dWih, dWhh, dbih, dbhh, oW, ob, out, T);
}